// round 15
// baseline (speedup 1.0000x reference)
#include <cuda_runtime.h>

// Beamform_1649267442279 — GB300 sm_103a — R15: R14 (58.4us kernel, DRAM
// 82.7%) restructured as a one-wave grid-stride loop: 740 CTAs (5/SM x 148),
// each walking ~21 tile positions. No syncs, stores are fire-and-forget ->
// iteration k+1's 8 front-batched loads issue while iteration k's are still
// draining (cross-iteration MLP beyond the 8-register-resident limit), and
// the ~20 wave transitions of the 15628-CTA grid disappear.
// Memory pattern per iteration is byte-identical to R14:
//  - thread handles col j of blocks b and b + Bc/2 (two compact 1KB windows)
//  - 8 independent LDG.64 front-batched
//  - __stcs streaming stores
//
// Semantics: per channel s, blocks of 20 complex samples (40 floats).
// Block b, row r (0..3), col c (0..4):
//   re[r,c] = in_s[40b + 10r + 2c],  im[r,c] = in_s[40b + 10r + 2c + 1]
//   out[(s*Bc+b)*10 + c]     = sum_r br[r]*re - bi[r]*im
//   out[(s*Bc+b)*10 + 5 + c] = sum_r bi[r]*re + br[r]*im
// with br[r]=bf[2r], bi[r]=bf[2r+1].

#define THREADS 320
#define BLK_PER_CTA (THREADS / 5)    // 64 blocks per tile position

__global__ void __launch_bounds__(THREADS)
beamform_kernel(const float* __restrict__ in0,
                const float* __restrict__ in1,
                const float* __restrict__ in2,
                const float* __restrict__ in3,
                const float* __restrict__ bf,
                float* __restrict__ out,
                int half_blocks,       // Bc / 2
                int blocks_per_ch)     // Bc
{
    const int t = threadIdx.x;
    const int b_loc = t / 5;                       // 0..63
    const int j     = t - b_loc * 5;               // 0..4

    const int ch = blockIdx.y;
    const float* __restrict__ in =
        (ch == 0) ? in0 : (ch == 1) ? in1 : (ch == 2) ? in2 : in3;

    // weights: uniform-address broadcast, L1-resident
    const float4 w0 = __ldg((const float4*)bf);      // br0, bi0, br1, bi1
    const float4 w1 = __ldg((const float4*)bf + 1);  // br2, bi2, br3, bi3

    const int stride_blocks = gridDim.x * BLK_PER_CTA;
    const size_t half_f2   = (size_t)half_blocks * 20;   // float2 per half
    const size_t half_out  = (size_t)half_blocks * 10;

    for (int b = blockIdx.x * BLK_PER_CTA + b_loc;
         b < half_blocks;
         b += stride_blocks)
    {
        // ---- front-batched loads: 8 independent LDG.64, two 1KB windows ----
        const float2* __restrict__ pA =
            (const float2*)(in + (size_t)b * 40 + 2 * j);
        const float2* __restrict__ pB = pA + half_f2;   // block b + Bc/2

        const float2 a0 = __ldg(pA + 0);
        const float2 a1 = __ldg(pA + 5);
        const float2 a2 = __ldg(pA + 10);
        const float2 a3 = __ldg(pA + 15);
        const float2 c0 = __ldg(pB + 0);
        const float2 c1 = __ldg(pB + 5);
        const float2 c2 = __ldg(pB + 10);
        const float2 c3 = __ldg(pB + 15);

        float reA = w0.x * a0.x - w0.y * a0.y;
        float imA = w0.y * a0.x + w0.x * a0.y;
        reA += w0.z * a1.x - w0.w * a1.y;
        imA += w0.w * a1.x + w0.z * a1.y;
        reA += w1.x * a2.x - w1.y * a2.y;
        imA += w1.y * a2.x + w1.x * a2.y;
        reA += w1.z * a3.x - w1.w * a3.y;
        imA += w1.w * a3.x + w1.z * a3.y;

        float reB = w0.x * c0.x - w0.y * c0.y;
        float imB = w0.y * c0.x + w0.x * c0.y;
        reB += w0.z * c1.x - w0.w * c1.y;
        imB += w0.w * c1.x + w0.z * c1.y;
        reB += w1.x * c2.x - w1.y * c2.y;
        imB += w1.y * c2.x + w1.x * c2.y;
        reB += w1.z * c3.x - w1.w * c3.y;
        imB += w1.w * c3.x + w1.z * c3.y;

        const size_t obA = ((size_t)ch * blocks_per_ch + (size_t)b) * 10;
        const size_t obB = obA + half_out;

        // streaming stores: output is never re-read, don't pollute L2
        __stcs(out + obA + j,     reA);
        __stcs(out + obA + 5 + j, imA);
        __stcs(out + obB + j,     reB);
        __stcs(out + obB + 5 + j, imB);
    }
}

extern "C" void kernel_launch(void* const* d_in, const int* in_sizes, int n_in,
                              void* d_out, int out_size)
{
    const float* in0 = (const float*)d_in[0];
    const float* in1 = (const float*)d_in[1];
    const float* in2 = (const float*)d_in[2];
    const float* in3 = (const float*)d_in[3];
    const float* bf  = (const float*)d_in[4];
    float* out = (float*)d_out;

    const int N  = in_sizes[0];          // 20,000,000 floats / channel
    const int Bc = N / 40;               // 500,000 beam blocks per channel
    const int Hb = Bc / 2;               // 250,000 blocks in each half

    // One resident wave: 148 SMs x 5 CTAs (320 thr, 32 regs) = 740 CTAs.
    // grid (185, 4): 185 CTAs walk each channel's first half with stride.
    dim3 grid(185, 4);
    beamform_kernel<<<grid, THREADS>>>(in0, in1, in2, in3, bf, out, Hb, Bc);
}

// round 16
// speedup vs baseline: 1.0702x; 1.0702x over previous
#include <cuda_runtime.h>

// Beamform_1649267442279 — GB300 sm_103a — FINAL (== R14/R8, the empirical
// optimum across 15 rounds: 58.4us kernel, DRAM 82.7%, HBM 6.55 TB/s,
// 61.92us wall).
//
// Why this shape won (established experimentally):
//  - Direct LDG.64, no smem staging: staging/syncs cost more than the 4x
//    per-line L1 re-touch they remove (R2, R10, R12 all slower).
//  - MLP=8 per thread via two HALF-CHANNEL-SPACED blocks: keeps every warp
//    LDG window at 1KB/8 lines (adjacent pairing doubles it, R4 slower);
//    MLP 12/16 cost registers -> occupancy, net loss (R6/R7/R9).
//  - __stcs streaming stores: output never re-read; keeps L2 ways for the
//    input-line reuse (+0.8% DRAM, R8).
//  - 320 threads: (block, col) split from threadIdx.x, no global div.
//  - Launch-indexed grid, single kernel node: grid-stride serializes
//    iterations at 32 regs (R15 slower); extra graph nodes cost ~4us wall
//    (R13).
//
// Semantics: per channel s, blocks of 20 complex samples (40 floats).
// Block b, row r (0..3), col c (0..4):
//   re[r,c] = in_s[40b + 10r + 2c],  im[r,c] = in_s[40b + 10r + 2c + 1]
//   out[(s*Bc+b)*10 + c]     = sum_r br[r]*re - bi[r]*im
//   out[(s*Bc+b)*10 + 5 + c] = sum_r bi[r]*re + br[r]*im
// with br[r]=bf[2r], bi[r]=bf[2r+1].

#define THREADS 320

__global__ void __launch_bounds__(THREADS)
beamform_kernel(const float* __restrict__ in0,
                const float* __restrict__ in1,
                const float* __restrict__ in2,
                const float* __restrict__ in3,
                const float* __restrict__ bf,
                float* __restrict__ out,
                int half_blocks,       // Bc / 2
                int blocks_per_ch)     // Bc
{
    const int t = threadIdx.x;
    // 320 % 5 == 0: per-CTA block base is blockIdx.x * 64, j from t only.
    const int b_loc = t / 5;                       // 0..63
    const int j     = t - b_loc * 5;               // 0..4
    const int b     = blockIdx.x * (THREADS / 5) + b_loc;
    if (b >= half_blocks) return;

    const int ch = blockIdx.y;
    const float* __restrict__ in =
        (ch == 0) ? in0 : (ch == 1) ? in1 : (ch == 2) ? in2 : in3;

    // ---- front-batched loads: 8 independent LDG.64, two compact windows ----
    const float2* __restrict__ pA =
        (const float2*)(in + (size_t)b * 40 + 2 * j);
    const float2* __restrict__ pB = pA + (size_t)half_blocks * 20;  // +Bc/2

    const float2 a0 = __ldg(pA + 0);
    const float2 a1 = __ldg(pA + 5);
    const float2 a2 = __ldg(pA + 10);
    const float2 a3 = __ldg(pA + 15);
    const float2 c0 = __ldg(pB + 0);
    const float2 c1 = __ldg(pB + 5);
    const float2 c2 = __ldg(pB + 10);
    const float2 c3 = __ldg(pB + 15);

    // weights: uniform-address broadcast, L1-resident
    const float4 w0 = __ldg((const float4*)bf);      // br0, bi0, br1, bi1
    const float4 w1 = __ldg((const float4*)bf + 1);  // br2, bi2, br3, bi3

    float reA = w0.x * a0.x - w0.y * a0.y;
    float imA = w0.y * a0.x + w0.x * a0.y;
    reA += w0.z * a1.x - w0.w * a1.y;
    imA += w0.w * a1.x + w0.z * a1.y;
    reA += w1.x * a2.x - w1.y * a2.y;
    imA += w1.y * a2.x + w1.x * a2.y;
    reA += w1.z * a3.x - w1.w * a3.y;
    imA += w1.w * a3.x + w1.z * a3.y;

    float reB = w0.x * c0.x - w0.y * c0.y;
    float imB = w0.y * c0.x + w0.x * c0.y;
    reB += w0.z * c1.x - w0.w * c1.y;
    imB += w0.w * c1.x + w0.z * c1.y;
    reB += w1.x * c2.x - w1.y * c2.y;
    imB += w1.y * c2.x + w1.x * c2.y;
    reB += w1.z * c3.x - w1.w * c3.y;
    imB += w1.w * c3.x + w1.z * c3.y;

    const size_t obA = ((size_t)ch * blocks_per_ch + (size_t)b) * 10;
    const size_t obB = obA + (size_t)half_blocks * 10;

    // streaming stores: output is never re-read, don't pollute L2
    __stcs(out + obA + j,     reA);
    __stcs(out + obA + 5 + j, imA);
    __stcs(out + obB + j,     reB);
    __stcs(out + obB + 5 + j, imB);
}

extern "C" void kernel_launch(void* const* d_in, const int* in_sizes, int n_in,
                              void* d_out, int out_size)
{
    const float* in0 = (const float*)d_in[0];
    const float* in1 = (const float*)d_in[1];
    const float* in2 = (const float*)d_in[2];
    const float* in3 = (const float*)d_in[3];
    const float* bf  = (const float*)d_in[4];
    float* out = (float*)d_out;

    const int N  = in_sizes[0];          // 20,000,000 floats / channel
    const int Bc = N / 40;               // 500,000 beam blocks per channel
    const int Hb = Bc / 2;               // 250,000 blocks in each half

    const int blocks_per_cta = THREADS / 5;                 // 64
    dim3 grid((Hb + blocks_per_cta - 1) / blocks_per_cta,   // 3907
              4);

    beamform_kernel<<<grid, THREADS>>>(in0, in1, in2, in3, bf, out, Hb, Bc);
}

// round 17
// speedup vs baseline: 1.0714x; 1.0010x over previous
#include <cuda_runtime.h>

// Beamform_1649267442279 — GB300 sm_103a — FINAL (R8/R14/R16 structure; the
// empirical optimum across 16 rounds: 58.4-59.5us kernel, DRAM 81-83%,
// HBM ~6.5 TB/s, 61.92us wall).
//
// Why this shape won (established experimentally):
//  - Direct LDG.64, no smem staging: staging/syncs cost more than the 4x
//    per-line L1 re-touch they remove (R2, R10, R12 all slower).
//  - ~82% DRAM-active is the HBM-side ceiling for this 4:1 R/W mix:
//    perfectly-coalesced cp.async versions (L1 ~40%) got LOWER DRAM,
//    proving the request side is not binding.
//  - MLP=8 per thread via two HALF-CHANNEL-SPACED blocks: keeps every warp
//    LDG window at 1KB/8 lines (adjacent pairing doubles it, R4 slower);
//    MLP 12/16 cost registers -> occupancy, net loss (R6/R7/R9).
//  - __stcs streaming stores: output never re-read; keeps L2 ways for the
//    input-line reuse (+0.8% DRAM, R8).
//  - 320 threads: (block, col) split from threadIdx.x, no global div.
//  - Launch-indexed grid, single kernel node: grid-stride serializes
//    iterations at 32 regs (R15 slower); extra graph nodes cost ~4us wall
//    (R13).
//
// Semantics: per channel s, blocks of 20 complex samples (40 floats).
// Block b, row r (0..3), col c (0..4):
//   re[r,c] = in_s[40b + 10r + 2c],  im[r,c] = in_s[40b + 10r + 2c + 1]
//   out[(s*Bc+b)*10 + c]     = sum_r br[r]*re - bi[r]*im
//   out[(s*Bc+b)*10 + 5 + c] = sum_r bi[r]*re + br[r]*im
// with br[r]=bf[2r], bi[r]=bf[2r+1].

#define THREADS 320

__global__ void __launch_bounds__(THREADS)
beamform_kernel(const float* __restrict__ in0,
                const float* __restrict__ in1,
                const float* __restrict__ in2,
                const float* __restrict__ in3,
                const float* __restrict__ bf,
                float* __restrict__ out,
                int half_blocks,       // Bc / 2
                int blocks_per_ch)     // Bc
{
    const int t = threadIdx.x;
    // 320 % 5 == 0: per-CTA block base is blockIdx.x * 64, j from t only.
    const int b_loc = t / 5;                       // 0..63
    const int j     = t - b_loc * 5;               // 0..4
    const int b     = blockIdx.x * (THREADS / 5) + b_loc;
    if (b >= half_blocks) return;

    const int ch = blockIdx.y;
    const float* __restrict__ in =
        (ch == 0) ? in0 : (ch == 1) ? in1 : (ch == 2) ? in2 : in3;

    // ---- front-batched loads: 8 independent LDG.64, two compact windows ----
    const float2* __restrict__ pA =
        (const float2*)(in + (size_t)b * 40 + 2 * j);
    const float2* __restrict__ pB = pA + (size_t)half_blocks * 20;  // +Bc/2

    const float2 a0 = __ldg(pA + 0);
    const float2 a1 = __ldg(pA + 5);
    const float2 a2 = __ldg(pA + 10);
    const float2 a3 = __ldg(pA + 15);
    const float2 c0 = __ldg(pB + 0);
    const float2 c1 = __ldg(pB + 5);
    const float2 c2 = __ldg(pB + 10);
    const float2 c3 = __ldg(pB + 15);

    // weights: uniform-address broadcast, L1-resident
    const float4 w0 = __ldg((const float4*)bf);      // br0, bi0, br1, bi1
    const float4 w1 = __ldg((const float4*)bf + 1);  // br2, bi2, br3, bi3

    float reA = w0.x * a0.x - w0.y * a0.y;
    float imA = w0.y * a0.x + w0.x * a0.y;
    reA += w0.z * a1.x - w0.w * a1.y;
    imA += w0.w * a1.x + w0.z * a1.y;
    reA += w1.x * a2.x - w1.y * a2.y;
    imA += w1.y * a2.x + w1.x * a2.y;
    reA += w1.z * a3.x - w1.w * a3.y;
    imA += w1.w * a3.x + w1.z * a3.y;

    float reB = w0.x * c0.x - w0.y * c0.y;
    float imB = w0.y * c0.x + w0.x * c0.y;
    reB += w0.z * c1.x - w0.w * c1.y;
    imB += w0.w * c1.x + w0.z * c1.y;
    reB += w1.x * c2.x - w1.y * c2.y;
    imB += w1.y * c2.x + w1.x * c2.y;
    reB += w1.z * c3.x - w1.w * c3.y;
    imB += w1.w * c3.x + w1.z * c3.y;

    const size_t obA = ((size_t)ch * blocks_per_ch + (size_t)b) * 10;
    const size_t obB = obA + (size_t)half_blocks * 10;

    // streaming stores: output is never re-read, don't pollute L2
    __stcs(out + obA + j,     reA);
    __stcs(out + obA + 5 + j, imA);
    __stcs(out + obB + j,     reB);
    __stcs(out + obB + 5 + j, imB);
}

extern "C" void kernel_launch(void* const* d_in, const int* in_sizes, int n_in,
                              void* d_out, int out_size)
{
    const float* in0 = (const float*)d_in[0];
    const float* in1 = (const float*)d_in[1];
    const float* in2 = (const float*)d_in[2];
    const float* in3 = (const float*)d_in[3];
    const float* bf  = (const float*)d_in[4];
    float* out = (float*)d_out;

    const int N  = in_sizes[0];          // 20,000,000 floats / channel
    const int Bc = N / 40;               // 500,000 beam blocks per channel
    const int Hb = Bc / 2;               // 250,000 blocks in each half

    const int blocks_per_cta = THREADS / 5;                 // 64
    dim3 grid((Hb + blocks_per_cta - 1) / blocks_per_cta,   // 3907
              4);

    beamform_kernel<<<grid, THREADS>>>(in0, in1, in2, in3, bf, out, Hb, Bc);
}